// round 9
// baseline (speedup 1.0000x reference)
#include <cuda_runtime.h>
#include <cuda_fp16.h>
#include <math.h>
#include <stdint.h>

#define B_ 8192
#define H_ 896
#define S_ 448
#define Q_ 256

// ---------------- scratch (allocation-free __device__ globals) ----------------
__device__ float g_R[3ull * B_ * H_];                    // R_u | R_r | R_e
__device__ __half g_Ah[(size_t)B_ * H_];
__device__ __half g_Hh[(size_t)B_ * H_];
__device__ __half g_Hl[(size_t)B_ * H_];
__device__ __half g_Th[2ull * B_ * S_];
__device__ __half g_Tl[2ull * B_ * S_];
#define WSZ (3 * H_ * H_ + 2 * S_ * S_ + 2 * Q_ * S_)
__device__ __half g_Wh[WSZ];

#define OFF_WR  0
#define OFF_WO1 (3 * H_ * H_)
#define OFF_WO2 (3 * H_ * H_ + 2 * S_ * S_)

// ---------------- PTX helpers (base sm_80+ features only) ----------------
__device__ __forceinline__ uint32_t s2u(const void* p) {
    return (uint32_t)__cvta_generic_to_shared(p);
}
__device__ __forceinline__ void cp_async16(uint32_t dst, const void* src, uint32_t bytes) {
    asm volatile("cp.async.cg.shared.global [%0], [%1], 16, %2;"
                 :: "r"(dst), "l"(src), "r"(bytes) : "memory");
}
__device__ __forceinline__ void cp_commit() {
    asm volatile("cp.async.commit_group;" ::: "memory");
}
template<int NN>
__device__ __forceinline__ void cp_wait() {
    asm volatile("cp.async.wait_group %0;" :: "n"(NN) : "memory");
}
__device__ __forceinline__ void ldm_x4(uint32_t* r, uint32_t addr) {
    asm volatile("ldmatrix.sync.aligned.m8n8.x4.shared.b16 {%0,%1,%2,%3}, [%4];"
                 : "=r"(r[0]), "=r"(r[1]), "=r"(r[2]), "=r"(r[3]) : "r"(addr));
}
__device__ __forceinline__ void mma_fp16(float* d, const uint32_t* a, uint32_t b0, uint32_t b1) {
    asm volatile("mma.sync.aligned.m16n8k16.row.col.f32.f16.f16.f32 "
                 "{%0,%1,%2,%3}, {%4,%5,%6,%7}, {%8,%9}, {%0,%1,%2,%3};"
                 : "+f"(d[0]), "+f"(d[1]), "+f"(d[2]), "+f"(d[3])
                 : "r"(a[0]), "r"(a[1]), "r"(a[2]), "r"(a[3]), "r"(b0), "r"(b1));
}
__device__ __forceinline__ float ftanh(float x) {
    float y; asm("tanh.approx.f32 %0, %1;" : "=f"(y) : "f"(x)); return y;
}
__device__ __forceinline__ float fsigm(float x) {
    return 1.0f / (1.0f + __expf(-x));
}

// ---------------- GEMM: C[M,N] = (Ah [+ Al])[M,K] @ Wh[N,K]^T -----------------
// CTA tile 256(m) x 128(n) x 32(k); 8 warps as 4m x 2n -> 64x64 warp tiles
// (LDSM:MMA ratio 16:64 per warp-chunk -> tensor pipe dominant, not smem).
// cp.async pipeline with LOOK = NST-2 (loads issued BEFORE the per-chunk
// barrier; write target (c+LOOK)%NST must differ from (c-1)%NST).
// TERMS=1: pure fp16 A. TERMS=2: A split hi/lo (2 MMA terms).
// stage: Ah(16K) [| Al(16K)] | Wh(8K)
// EPI: 0 = fp32, 1 = +bias fp32, 2 = relu(+bias) -> fp16 hi/lo pair
// grid.z batches two independent GEMMs (zA/zW/zC element strides, bias0/bias1).
template<int EPI, bool SPLITC, int TERMS>
__global__ __launch_bounds__(256, 1)
void gemm_mma(const __half* __restrict__ Ah, const __half* __restrict__ Al, int lda,
              const __half* __restrict__ Wh,
              int N, int K, const float* __restrict__ bias0, const float* __restrict__ bias1,
              float* __restrict__ Cf, __half* __restrict__ Chi,
              __half* __restrict__ Clo, int ldc,
              int zA, int zW, int zC)
{
    constexpr int WOFS   = TERMS * 16384;
    constexpr int SBYTES = WOFS + 8192;
    constexpr int NST    = (TERMS == 2) ? 4 : 5;
    constexpr int LOOK   = NST - 2;          // max safe lookahead (see header)

    extern __shared__ char smem[];
    const int z = blockIdx.z;
    Ah += (size_t)z * zA;
    if (TERMS == 2) Al += (size_t)z * zA;
    Wh += (size_t)z * zW;
    const float* bias = z ? bias1 : bias0;

    const int t  = threadIdx.x;
    const int m0 = blockIdx.y * 256;
    const int n0 = blockIdx.x * 128;
    const int tile_n = SPLITC ? 128 : min(128, N - n0);
    const uint32_t sb0 = s2u(smem);
    const int lane = t & 31;
    const int wid  = t >> 5;
    const int wm = (wid & 3) * 64;   // 4 warps along m
    const int wn = (wid >> 2) * 64;  // 2 warps along n

    float acc[4][8][4];
#pragma unroll
    for (int a = 0; a < 4; a++)
#pragma unroll
        for (int b = 0; b < 8; b++)
#pragma unroll
            for (int d = 0; d < 4; d++) acc[a][b][d] = 0.f;

    const int nch = K / 32;

    auto load_stage = [&](int c, int st) {
        const int k0 = c * 32;
        const uint32_t sb = sb0 + st * SBYTES;
#pragma unroll
        for (int i = 0; i < 4 * TERMS; ++i) {      // A tiles: 256 rows x 4 chunks
            const int term   = i >> 2;
            const int within = t + (i & 3) * 256;  // 0..1023
            const int row    = within >> 2;        // 0..255
            const int ch     = within & 3;
            const uint32_t dst = sb + term * 16384 + row * 64 +
                                 ((ch ^ ((row >> 1) & 3)) * 16);
            const __half* base = (term == 0) ? Ah : Al;
            cp_async16(dst, base + (size_t)(m0 + row) * lda + k0 + ch * 8, 16);
        }
#pragma unroll
        for (int i = 0; i < 2; ++i) {              // W tile: 128 rows x 4 chunks
            const int within = t + i * 256;        // 0..511
            const int row    = within >> 2;        // 0..127
            const int ch     = within & 3;
            const uint32_t dst = sb + WOFS + row * 64 +
                                 ((ch ^ ((row >> 1) & 3)) * 16);
            const int r = (row < tile_n) ? row : (tile_n - 1);
            cp_async16(dst, Wh + (size_t)(n0 + r) * K + k0 + ch * 8,
                       (row < tile_n) ? 16u : 0u);
        }
        cp_commit();
    };

#pragma unroll
    for (int s = 0; s < LOOK; ++s)
        if (s < nch) load_stage(s, s);

    const int arow = (lane & 7) + ((lane >> 3) & 1) * 8;
    const int asel = (lane >> 4) & 1;
    const int brow = (lane & 7) + ((lane >> 4) & 1) * 8;
    const int bsel = (lane >> 3) & 1;

    for (int c = 0; c < nch; ++c) {
        if (c + LOOK < nch) { load_stage(c + LOOK, (c + LOOK) % NST); cp_wait<LOOK>(); }
        else {
            const int rem = nch - 1 - c;    // 0..LOOK-1
            if (rem >= 2)      cp_wait<2>();
            else if (rem == 1) cp_wait<1>();
            else               cp_wait<0>();
        }
        __syncthreads();
        const uint32_t sb = sb0 + (c % NST) * SBYTES;
#pragma unroll
        for (int ks = 0; ks < 2; ++ks) {
            uint32_t ahf[4][4], alf[4][4];
            const int ach = ks * 2 + asel;
#pragma unroll
            for (int mt = 0; mt < 4; ++mt) {
                const int row = wm + mt * 16 + arow;
                const uint32_t ad = sb + row * 64 + ((ach ^ ((row >> 1) & 3)) * 16);
                ldm_x4(ahf[mt], ad);
                if (TERMS == 2) ldm_x4(alf[mt], ad + 16384);
            }
            const int bch = ks * 2 + bsel;
#pragma unroll
            for (int hb = 0; hb < 2; ++hb) {
                uint32_t bhf[2][4];
#pragma unroll
                for (int p = 0; p < 2; ++p) {
                    const int nrow = wn + hb * 32 + p * 16 + brow;
                    const uint32_t bd = sb + WOFS + nrow * 64 +
                                        ((bch ^ ((nrow >> 1) & 3)) * 16);
                    ldm_x4(bhf[p], bd);
                }
#pragma unroll
                for (int mt = 0; mt < 4; ++mt)
#pragma unroll
                    for (int q = 0; q < 4; ++q)
                        mma_fp16(acc[mt][hb * 4 + q], ahf[mt],
                                 bhf[q >> 1][(q & 1) * 2], bhf[q >> 1][(q & 1) * 2 + 1]);
                if (TERMS == 2) {
#pragma unroll
                    for (int mt = 0; mt < 4; ++mt)
#pragma unroll
                        for (int q = 0; q < 4; ++q)
                            mma_fp16(acc[mt][hb * 4 + q], alf[mt],
                                     bhf[q >> 1][(q & 1) * 2], bhf[q >> 1][(q & 1) * 2 + 1]);
                }
            }
        }
    }

    // ---- epilogue
    float* Cf2 = Cf + (size_t)z * zC;
    __half* Chi2 = Chi + (size_t)z * zC;
    __half* Clo2 = Clo + (size_t)z * zC;
    int ncol0 = n0;
    if (SPLITC) {
        const int g = n0 / H_;
        Cf2 = Cf + (size_t)g * B_ * H_;
        ncol0 = n0 - g * H_;
    }
    const int gid = lane >> 2;
    const int cp2 = (lane & 3) * 2;
#pragma unroll
    for (int mt = 0; mt < 4; ++mt) {
        const int r0 = m0 + wm + mt * 16 + gid;
#pragma unroll
        for (int nt = 0; nt < 8; ++nt) {
            const int cloc = wn + nt * 8 + cp2;
            if (SPLITC || n0 + cloc < N) {
                const int col = ncol0 + cloc;
                float x0 = acc[mt][nt][0], x1 = acc[mt][nt][1];
                float x2 = acc[mt][nt][2], x3 = acc[mt][nt][3];
                if (EPI >= 1) {
                    const float bb0 = bias[col], bb1 = bias[col + 1];
                    x0 += bb0; x1 += bb1; x2 += bb0; x3 += bb1;
                }
                if (EPI == 2) {
                    x0 = fmaxf(x0, 0.f); x1 = fmaxf(x1, 0.f);
                    x2 = fmaxf(x2, 0.f); x3 = fmaxf(x3, 0.f);
                    __half h0 = __float2half(x0), h1 = __float2half(x1);
                    __half h2 = __float2half(x2), h3 = __float2half(x3);
                    __half l0 = __float2half(x0 - __half2float(h0));
                    __half l1 = __float2half(x1 - __half2float(h1));
                    __half l2 = __float2half(x2 - __half2float(h2));
                    __half l3 = __float2half(x3 - __half2float(h3));
                    *(__half2*)(Chi2 + (size_t)r0 * ldc + col)       = __halves2half2(h0, h1);
                    *(__half2*)(Chi2 + (size_t)(r0 + 8) * ldc + col) = __halves2half2(h2, h3);
                    *(__half2*)(Clo2 + (size_t)r0 * ldc + col)       = __halves2half2(l0, l1);
                    *(__half2*)(Clo2 + (size_t)(r0 + 8) * ldc + col) = __halves2half2(l2, l3);
                } else {
                    *(float2*)(Cf2 + (size_t)r0 * ldc + col)       = make_float2(x0, x1);
                    *(float2*)(Cf2 + (size_t)(r0 + 8) * ldc + col) = make_float2(x2, x3);
                }
            }
        }
    }
}

// ---------------- fp32 -> fp16 (vec4) ----------------
__global__ void cvtW_kernel(const float4* __restrict__ src,
                            __half* __restrict__ dst, int n4)
{
    int i = blockIdx.x * blockDim.x + threadIdx.x;
    if (i < n4) {
        float4 x = src[i];
        __half h[4];
        h[0] = __float2half(x.x); h[1] = __float2half(x.y);
        h[2] = __float2half(x.z); h[3] = __float2half(x.w);
        *(uint2*)(dst + 4 * (size_t)i) = *(uint2*)h;
    }
}

// merged convert: 3 recurrent weight mats -> packed fp16
__global__ void cvtWR3_kernel(const float4* __restrict__ s0, const float4* __restrict__ s1,
                              const float4* __restrict__ s2, __half* __restrict__ dst)
{
    const int n4 = H_ * H_ / 4;
    int i = blockIdx.x * blockDim.x + threadIdx.x;
    if (i >= 3 * n4) return;
    const int sel = i / n4;
    const int j = i - sel * n4;
    const float4* s = (sel == 0) ? s0 : (sel == 1) ? s1 : s2;
    float4 x = s[j];
    __half h[4];
    h[0] = __float2half(x.x); h[1] = __float2half(x.y);
    h[2] = __float2half(x.z); h[3] = __float2half(x.w);
    *(uint2*)(dst + 4 * (size_t)i) = *(uint2*)h;
}

// merged convert: 4 output-MLP weight mats -> packed fp16 (vec4)
__global__ void cvtW4_kernel(const float4* __restrict__ s0, const float4* __restrict__ s1,
                             const float4* __restrict__ s2, const float4* __restrict__ s3,
                             __half* __restrict__ dst)
{
    const int n0 = S_ * S_ / 4, n1 = 2 * (S_ * S_ / 4);
    const int n2 = n1 + Q_ * S_ / 4, n3 = n1 + 2 * (Q_ * S_ / 4);
    int i = blockIdx.x * blockDim.x + threadIdx.x;
    if (i >= n3) return;
    float4 x;
    if      (i < n0) x = s0[i];
    else if (i < n1) x = s1[i - n0];
    else if (i < n2) x = s2[i - n1];
    else             x = s3[i - n2];
    __half h[4];
    h[0] = __float2half(x.x); h[1] = __float2half(x.y);
    h[2] = __float2half(x.z); h[3] = __float2half(x.w);
    *(uint2*)(dst + 4 * (size_t)i) = *(uint2*)h;
}

// ---------------- fused gate (vectorized x4, fast math) ----------------
__global__ void gate_kernel(const float* __restrict__ prev_y,
                            const float* __restrict__ prev_hidden,
                            const float* __restrict__ coarse,
                            const float* __restrict__ W_Ic,
                            const float* __restrict__ W_If,
                            const float* __restrict__ bias_u,
                            const float* __restrict__ bias_r,
                            const float* __restrict__ bias_e,
                            const float* __restrict__ Rbuf,
                            float* __restrict__ hidden_out,
                            __half* __restrict__ hid_hi,
                            __half* __restrict__ hid_lo)
{
    const int HV = H_ / 4;
    int v = blockIdx.x * blockDim.x + threadIdx.x;
    if (v >= B_ * HV) return;
    int b = v / HV;
    int j = (v - b * HV) * 4;
    size_t idx = (size_t)b * H_ + j;
    const size_t NBH = (size_t)B_ * H_;

    float py0 = prev_y[2 * b], py1 = prev_y[2 * b + 1];
    float4 Ru4 = *(const float4*)(Rbuf + idx);
    float4 Rr4 = *(const float4*)(Rbuf + NBH + idx);
    float4 Re4 = *(const float4*)(Rbuf + 2 * NBH + idx);
    float4 ph4 = *(const float4*)(prev_hidden + idx);

    float h[4];
    const float* Ru = (const float*)&Ru4;
    const float* Rr = (const float*)&Rr4;
    const float* Re = (const float*)&Re4;
    const float* ph = (const float*)&ph4;

    if (j < S_) {
#pragma unroll
        for (int q = 0; q < 4; ++q) {
            int jj = j + q;
            float Iu = py0 * W_Ic[jj * 2] + py1 * W_Ic[jj * 2 + 1];
            float Ir = py0 * W_Ic[(S_ + jj) * 2] + py1 * W_Ic[(S_ + jj) * 2 + 1];
            float Ie = py0 * W_Ic[(2 * S_ + jj) * 2] + py1 * W_Ic[(2 * S_ + jj) * 2 + 1];
            float u = fsigm(Ru[q] + Iu + bias_u[jj]);
            float r = fsigm(Rr[q] + Ir + bias_r[jj]);
            float e = ftanh(r * Re[q] + Ie + bias_e[jj]);
            h[q] = u * ph[q] + (1.f - u) * e;
        }
    } else {
        float cc = coarse[b];
#pragma unroll
        for (int q = 0; q < 4; ++q) {
            int jj = j + q;
            int jf = jj - S_;
            float Iu = py0 * W_If[jf * 3] + py1 * W_If[jf * 3 + 1] + cc * W_If[jf * 3 + 2];
            float Ir = py0 * W_If[(S_ + jf) * 3] + py1 * W_If[(S_ + jf) * 3 + 1] + cc * W_If[(S_ + jf) * 3 + 2];
            float Ie = py0 * W_If[(2 * S_ + jf) * 3] + py1 * W_If[(2 * S_ + jf) * 3 + 1] + cc * W_If[(2 * S_ + jf) * 3 + 2];
            float u = fsigm(Ru[q] + Iu + bias_u[jj]);
            float r = fsigm(Rr[q] + Ir + bias_r[jj]);
            float e = ftanh(r * Re[q] + Ie + bias_e[jj]);
            h[q] = u * ph[q] + (1.f - u) * e;
        }
    }

    *(float4*)(hidden_out + idx) = make_float4(h[0], h[1], h[2], h[3]);

    __half hh[4], hl[4];
#pragma unroll
    for (int q = 0; q < 4; ++q) {
        __half hi = __float2half(h[q]);
        hh[q] = hi;
        hl[q] = __float2half(h[q] - __half2float(hi));
    }
    *(uint2*)(hid_hi + idx) = *(uint2*)hh;
    *(uint2*)(hid_lo + idx) = *(uint2*)hl;
}

// ---------------- launch ----------------
extern "C" void kernel_launch(void* const* d_in, const int* in_sizes, int n_in,
                              void* d_out, int out_size)
{
    const float* prev_y      = (const float*)d_in[0];
    const float* prev_hidden = (const float*)d_in[1];
    const float* coarse      = (const float*)d_in[2];
    const float* W_Ru        = (const float*)d_in[3];
    const float* W_Rr        = (const float*)d_in[4];
    const float* W_Re        = (const float*)d_in[5];
    const float* W_Ic        = (const float*)d_in[6];
    const float* W_If        = (const float*)d_in[7];
    const float* W_O1        = (const float*)d_in[8];
    const float* b_O1        = (const float*)d_in[9];
    const float* W_O2        = (const float*)d_in[10];
    const float* b_O2        = (const float*)d_in[11];
    const float* W_O3        = (const float*)d_in[12];
    const float* b_O3        = (const float*)d_in[13];
    const float* W_O4        = (const float*)d_in[14];
    const float* b_O4        = (const float*)d_in[15];
    const float* bias_u      = (const float*)d_in[16];
    const float* bias_r      = (const float*)d_in[17];
    const float* bias_e      = (const float*)d_in[18];

    float* out        = (float*)d_out;
    float* out_coarse = out;
    float* hidden     = out + 2 * (size_t)B_ * Q_;

    float* Rbuf; __half *Ah, *Hh, *Hl, *Th, *Tl, *Wh;
    cudaGetSymbolAddress((void**)&Rbuf, g_R);
    cudaGetSymbolAddress((void**)&Ah, g_Ah);
    cudaGetSymbolAddress((void**)&Hh, g_Hh);
    cudaGetSymbolAddress((void**)&Hl, g_Hl);
    cudaGetSymbolAddress((void**)&Th, g_Th);
    cudaGetSymbolAddress((void**)&Tl, g_Tl);
    cudaGetSymbolAddress((void**)&Wh, g_Wh);

    const int SM1 = 5 * (16384 + 8192);   // 1-term: 5 stages x 24KB = 120KB
    const int SM2 = 4 * (32768 + 8192);   // 2-term: 4 stages x 40KB = 160KB
    cudaFuncSetAttribute(gemm_mma<0, true, 1>,  cudaFuncAttributeMaxDynamicSharedMemorySize, SM1);
    cudaFuncSetAttribute(gemm_mma<2, false, 2>, cudaFuncAttributeMaxDynamicSharedMemorySize, SM2);
    cudaFuncSetAttribute(gemm_mma<1, false, 2>, cudaFuncAttributeMaxDynamicSharedMemorySize, SM2);

    const int NBS = B_ * S_;
    dim3 blk(256);

    // converts (3 launches)
    cvtW_kernel<<<(B_ * H_ / 4 + 255) / 256, 256>>>((const float4*)prev_hidden, Ah, B_ * H_ / 4);
    cvtWR3_kernel<<<(3 * H_ * H_ / 4 + 255) / 256, 256>>>((const float4*)W_Ru, (const float4*)W_Rr,
                                                          (const float4*)W_Re, Wh + OFF_WR);
    cvtW4_kernel<<<((2 * S_ * S_ + 2 * Q_ * S_) / 4 + 255) / 256, 256>>>(
        (const float4*)W_O1, (const float4*)W_O3, (const float4*)W_O2, (const float4*)W_O4,
        Wh + OFF_WO1);

    // fused recurrent projections (1-term fp16), N = 3*H = 2688
    dim3 g1(3 * H_ / 128, B_ / 256, 1);  // (21, 32)
    gemm_mma<0, true, 1><<<g1, blk, SM1>>>(Ah, nullptr, H_, Wh + OFF_WR,
                                           3 * H_, H_, nullptr, nullptr,
                                           Rbuf, nullptr, nullptr, H_, 0, 0, 0);

    // fused gates -> hidden (fp32 to d_out) + fp16 hi/lo pair
    gate_kernel<<<(B_ * (H_ / 4) + 255) / 256, 256>>>(prev_y, prev_hidden, coarse, W_Ic, W_If,
                                                      bias_u, bias_r, bias_e, Rbuf, hidden, Hh, Hl);

    // relu(h_half @ W^T + b) -> fp16 pair scratch; z batches O1 / O3
    dim3 g2((S_ + 127) / 128, B_ / 256, 2);  // (4, 32, 2)
    gemm_mma<2, false, 2><<<g2, blk, SM2>>>(Hh, Hl, H_, Wh + OFF_WO1,
                                            S_, S_, b_O1, b_O3,
                                            nullptr, Th, Tl, S_,
                                            S_, S_ * S_, NBS);

    // logits -> d_out; z batches O2 / O4
    dim3 g3(Q_ / 128, B_ / 256, 2);  // (2, 32, 2)
    gemm_mma<1, false, 2><<<g3, blk, SM2>>>(Th, Tl, S_, Wh + OFF_WO2,
                                            Q_, S_, b_O2, b_O4,
                                            out_coarse, nullptr, nullptr, Q_,
                                            NBS, Q_ * S_, B_ * Q_);
}

// round 11
// speedup vs baseline: 1.2929x; 1.2929x over previous
#include <cuda_runtime.h>
#include <cuda_fp16.h>
#include <math.h>
#include <stdint.h>

#define B_ 8192
#define H_ 896
#define S_ 448
#define Q_ 256

// ---------------- scratch (allocation-free __device__ globals) ----------------
__device__ __half g_R[3ull * B_ * H_];       // R_u | R_r | R_e (fp16)
__device__ __half g_Ah[(size_t)B_ * H_];     // prev_hidden fp16
__device__ __half g_Hh[(size_t)B_ * H_];     // hidden fp16
__device__ __half g_Th[2ull * B_ * S_];      // relu(t1)|relu(t2) fp16
#define WSZ (3 * H_ * H_ + 2 * S_ * S_ + 2 * Q_ * S_)
__device__ __half g_Wh[WSZ];

#define OFF_WR  0
#define OFF_WO1 (3 * H_ * H_)
#define OFF_WO2 (3 * H_ * H_ + 2 * S_ * S_)

// ---------------- PTX helpers (base sm_80+ features only) ----------------
__device__ __forceinline__ uint32_t s2u(const void* p) {
    return (uint32_t)__cvta_generic_to_shared(p);
}
__device__ __forceinline__ void cp_async16(uint32_t dst, const void* src, uint32_t bytes) {
    asm volatile("cp.async.cg.shared.global [%0], [%1], 16, %2;"
                 :: "r"(dst), "l"(src), "r"(bytes) : "memory");
}
__device__ __forceinline__ void cp_commit() {
    asm volatile("cp.async.commit_group;" ::: "memory");
}
template<int NN>
__device__ __forceinline__ void cp_wait() {
    asm volatile("cp.async.wait_group %0;" :: "n"(NN) : "memory");
}
__device__ __forceinline__ void ldm_x4(uint32_t* r, uint32_t addr) {
    asm volatile("ldmatrix.sync.aligned.m8n8.x4.shared.b16 {%0,%1,%2,%3}, [%4];"
                 : "=r"(r[0]), "=r"(r[1]), "=r"(r[2]), "=r"(r[3]) : "r"(addr));
}
__device__ __forceinline__ void mma_fp16(float* d, const uint32_t* a, uint32_t b0, uint32_t b1) {
    asm volatile("mma.sync.aligned.m16n8k16.row.col.f32.f16.f16.f32 "
                 "{%0,%1,%2,%3}, {%4,%5,%6,%7}, {%8,%9}, {%0,%1,%2,%3};"
                 : "+f"(d[0]), "+f"(d[1]), "+f"(d[2]), "+f"(d[3])
                 : "r"(a[0]), "r"(a[1]), "r"(a[2]), "r"(a[3]), "r"(b0), "r"(b1));
}
__device__ __forceinline__ float ftanh(float x) {
    float y; asm("tanh.approx.f32 %0, %1;" : "=f"(y) : "f"(x)); return y;
}
__device__ __forceinline__ float fsigm(float x) {
    return 1.0f / (1.0f + __expf(-x));
}

// ---------------- GEMM: C[M,N] = A[M,K] @ W[N,K]^T (fp16 in, fp32 acc) --------
// R8-proven config: CTA 128x128x32, 8 warps as 4m x 2n (32x64 warp tiles),
// 2 CTAs/SM, 5-stage cp.async pipeline, LOOK = NST-2 = 3 (loads are issued
// BEFORE the per-chunk barrier; write target (c+LOOK)%NST != (c-1)%NST).
// stage: A(8K) | W(8K) = 16KB.
// EPI: 0 = fp16 store, 1 = +bias fp32 store, 2 = relu(+bias) -> fp16 store
// grid.z batches two independent GEMMs (zA/zW/zC element strides, bias0/bias1).
#define STAGE_BYTES 16384
#define NSTAGE 5
#define GLOOK  3
#define SMEM_TOTAL (NSTAGE * STAGE_BYTES)

template<int EPI, bool SPLITC>
__global__ __launch_bounds__(256, 2)
void gemm_mma(const __half* __restrict__ Ah, int lda,
              const __half* __restrict__ Wh,
              int N, int K, const float* __restrict__ bias0, const float* __restrict__ bias1,
              float* __restrict__ Cf, __half* __restrict__ Ch, int ldc,
              int zA, int zW, int zC)
{
    extern __shared__ char smem[];
    const int z = blockIdx.z;
    Ah += (size_t)z * zA;
    Wh += (size_t)z * zW;
    const float* bias = z ? bias1 : bias0;

    const int t  = threadIdx.x;
    const int m0 = blockIdx.y * 128;
    const int n0 = blockIdx.x * 128;
    const int tile_n = SPLITC ? 128 : min(128, N - n0);
    const uint32_t sb0 = s2u(smem);
    const int lane = t & 31;
    const int wid  = t >> 5;
    const int wm = (wid & 3) * 32;
    const int wn = (wid >> 2) * 64;

    float acc[2][8][4];
#pragma unroll
    for (int a = 0; a < 2; a++)
#pragma unroll
        for (int b = 0; b < 8; b++)
#pragma unroll
            for (int d = 0; d < 4; d++) acc[a][b][d] = 0.f;

    const int nch = K / 32;

    auto load_stage = [&](int c, int st) {
        const int k0 = c * 32;
        const uint32_t sb = sb0 + st * STAGE_BYTES;
#pragma unroll
        for (int i = 0; i < 4; ++i) {
            const int tile   = i >> 1;              // 0=A, 1=W
            const int within = t + (i & 1) * 256;   // 0..511
            const int row    = within >> 2;         // 0..127
            const int ch     = within & 3;
            const uint32_t dst = sb + tile * 8192 + row * 64 +
                                 ((ch ^ ((row >> 1) & 3)) * 16);
            if (tile == 0) {
                cp_async16(dst, Ah + (size_t)(m0 + row) * lda + k0 + ch * 8, 16);
            } else {
                const int r = (row < tile_n) ? row : (tile_n - 1);
                cp_async16(dst, Wh + (size_t)(n0 + r) * K + k0 + ch * 8,
                           (row < tile_n) ? 16u : 0u);
            }
        }
        cp_commit();
    };

#pragma unroll
    for (int s = 0; s < GLOOK; ++s)
        if (s < nch) load_stage(s, s);

    const int arow = (lane & 7) + ((lane >> 3) & 1) * 8;
    const int asel = (lane >> 4) & 1;
    const int brow = (lane & 7) + ((lane >> 4) & 1) * 8;
    const int bsel = (lane >> 3) & 1;

    for (int c = 0; c < nch; ++c) {
        if (c + GLOOK < nch) { load_stage(c + GLOOK, (c + GLOOK) % NSTAGE); cp_wait<GLOOK>(); }
        else {
            const int rem = nch - 1 - c;    // 0..GLOOK-1
            if (rem >= 2)      cp_wait<2>();
            else if (rem == 1) cp_wait<1>();
            else               cp_wait<0>();
        }
        __syncthreads();
        const uint32_t sb = sb0 + (c % NSTAGE) * STAGE_BYTES;
#pragma unroll
        for (int ks = 0; ks < 2; ++ks) {
            uint32_t ahf[2][4];
            const int ach = ks * 2 + asel;
#pragma unroll
            for (int mt = 0; mt < 2; ++mt) {
                const int row = wm + mt * 16 + arow;
                const uint32_t ad = sb + row * 64 + ((ach ^ ((row >> 1) & 3)) * 16);
                ldm_x4(ahf[mt], ad);
            }
            const int bch = ks * 2 + bsel;
#pragma unroll
            for (int hb = 0; hb < 2; ++hb) {
                uint32_t bhf[2][4];
#pragma unroll
                for (int p = 0; p < 2; ++p) {
                    const int nrow = wn + hb * 32 + p * 16 + brow;
                    const uint32_t bd = sb + 8192 + nrow * 64 +
                                        ((bch ^ ((nrow >> 1) & 3)) * 16);
                    ldm_x4(bhf[p], bd);
                }
#pragma unroll
                for (int mt = 0; mt < 2; ++mt)
#pragma unroll
                    for (int q = 0; q < 4; ++q)
                        mma_fp16(acc[mt][hb * 4 + q], ahf[mt],
                                 bhf[q >> 1][(q & 1) * 2], bhf[q >> 1][(q & 1) * 2 + 1]);
            }
        }
    }

    // ---- epilogue
    float*  Cf2 = Cf + (size_t)z * zC;
    __half* Ch2 = Ch + (size_t)z * zC;
    int ncol0 = n0;
    if (SPLITC) {
        const int g = n0 / H_;
        Ch2 = Ch + (size_t)g * B_ * H_;
        ncol0 = n0 - g * H_;
    }
    const int gid = lane >> 2;
    const int cp2 = (lane & 3) * 2;
#pragma unroll
    for (int mt = 0; mt < 2; ++mt) {
        const int r0 = m0 + wm + mt * 16 + gid;
#pragma unroll
        for (int nt = 0; nt < 8; ++nt) {
            const int cloc = wn + nt * 8 + cp2;
            if (SPLITC || n0 + cloc < N) {
                const int col = ncol0 + cloc;
                float x0 = acc[mt][nt][0], x1 = acc[mt][nt][1];
                float x2 = acc[mt][nt][2], x3 = acc[mt][nt][3];
                if (EPI >= 1) {
                    const float bb0 = bias[col], bb1 = bias[col + 1];
                    x0 += bb0; x1 += bb1; x2 += bb0; x3 += bb1;
                }
                if (EPI == 2) {
                    x0 = fmaxf(x0, 0.f); x1 = fmaxf(x1, 0.f);
                    x2 = fmaxf(x2, 0.f); x3 = fmaxf(x3, 0.f);
                }
                if (EPI == 1) {
                    *(float2*)(Cf2 + (size_t)r0 * ldc + col)       = make_float2(x0, x1);
                    *(float2*)(Cf2 + (size_t)(r0 + 8) * ldc + col) = make_float2(x2, x3);
                } else {
                    *(__half2*)(Ch2 + (size_t)r0 * ldc + col) =
                        __halves2half2(__float2half(x0), __float2half(x1));
                    *(__half2*)(Ch2 + (size_t)(r0 + 8) * ldc + col) =
                        __halves2half2(__float2half(x2), __float2half(x3));
                }
            }
        }
    }
}

// ---------------- fp32 -> fp16 (vec4) ----------------
__global__ void cvtW_kernel(const float4* __restrict__ src,
                            __half* __restrict__ dst, int n4)
{
    int i = blockIdx.x * blockDim.x + threadIdx.x;
    if (i < n4) {
        float4 x = src[i];
        __half h[4];
        h[0] = __float2half(x.x); h[1] = __float2half(x.y);
        h[2] = __float2half(x.z); h[3] = __float2half(x.w);
        *(uint2*)(dst + 4 * (size_t)i) = *(uint2*)h;
    }
}

// merged convert: 3 recurrent weight mats -> packed fp16
__global__ void cvtWR3_kernel(const float4* __restrict__ s0, const float4* __restrict__ s1,
                              const float4* __restrict__ s2, __half* __restrict__ dst)
{
    const int n4 = H_ * H_ / 4;
    int i = blockIdx.x * blockDim.x + threadIdx.x;
    if (i >= 3 * n4) return;
    const int sel = i / n4;
    const int j = i - sel * n4;
    const float4* s = (sel == 0) ? s0 : (sel == 1) ? s1 : s2;
    float4 x = s[j];
    __half h[4];
    h[0] = __float2half(x.x); h[1] = __float2half(x.y);
    h[2] = __float2half(x.z); h[3] = __float2half(x.w);
    *(uint2*)(dst + 4 * (size_t)i) = *(uint2*)h;
}

// merged convert: 4 output-MLP weight mats -> packed fp16 (vec4)
__global__ void cvtW4_kernel(const float4* __restrict__ s0, const float4* __restrict__ s1,
                             const float4* __restrict__ s2, const float4* __restrict__ s3,
                             __half* __restrict__ dst)
{
    const int n0 = S_ * S_ / 4, n1 = 2 * (S_ * S_ / 4);
    const int n2 = n1 + Q_ * S_ / 4, n3 = n1 + 2 * (Q_ * S_ / 4);
    int i = blockIdx.x * blockDim.x + threadIdx.x;
    if (i >= n3) return;
    float4 x;
    if      (i < n0) x = s0[i];
    else if (i < n1) x = s1[i - n0];
    else if (i < n2) x = s2[i - n1];
    else             x = s3[i - n2];
    __half h[4];
    h[0] = __float2half(x.x); h[1] = __float2half(x.y);
    h[2] = __float2half(x.z); h[3] = __float2half(x.w);
    *(uint2*)(dst + 4 * (size_t)i) = *(uint2*)h;
}

// ---------------- fused gate (vec x4, fast math, fp16 R input) ----------------
__global__ void gate_kernel(const float* __restrict__ prev_y,
                            const float* __restrict__ prev_hidden,
                            const float* __restrict__ coarse,
                            const float* __restrict__ W_Ic,
                            const float* __restrict__ W_If,
                            const float* __restrict__ bias_u,
                            const float* __restrict__ bias_r,
                            const float* __restrict__ bias_e,
                            const __half* __restrict__ Rbuf,
                            float* __restrict__ hidden_out,
                            __half* __restrict__ hid_h)
{
    const int HV = H_ / 4;
    int v = blockIdx.x * blockDim.x + threadIdx.x;
    if (v >= B_ * HV) return;
    int b = v / HV;
    int j = (v - b * HV) * 4;
    size_t idx = (size_t)b * H_ + j;
    const size_t NBH = (size_t)B_ * H_;

    float py0 = prev_y[2 * b], py1 = prev_y[2 * b + 1];

    __half Ru2[4], Rr2[4], Re2[4];
    *(uint2*)Ru2 = *(const uint2*)(Rbuf + idx);
    *(uint2*)Rr2 = *(const uint2*)(Rbuf + NBH + idx);
    *(uint2*)Re2 = *(const uint2*)(Rbuf + 2 * NBH + idx);
    float4 ph4 = *(const float4*)(prev_hidden + idx);
    const float* ph = (const float*)&ph4;

    float h[4];
    if (j < S_) {
#pragma unroll
        for (int q = 0; q < 4; ++q) {
            int jj = j + q;
            float Iu = py0 * W_Ic[jj * 2] + py1 * W_Ic[jj * 2 + 1];
            float Ir = py0 * W_Ic[(S_ + jj) * 2] + py1 * W_Ic[(S_ + jj) * 2 + 1];
            float Ie = py0 * W_Ic[(2 * S_ + jj) * 2] + py1 * W_Ic[(2 * S_ + jj) * 2 + 1];
            float u = fsigm(__half2float(Ru2[q]) + Iu + bias_u[jj]);
            float r = fsigm(__half2float(Rr2[q]) + Ir + bias_r[jj]);
            float e = ftanh(r * __half2float(Re2[q]) + Ie + bias_e[jj]);
            h[q] = u * ph[q] + (1.f - u) * e;
        }
    } else {
        float cc = coarse[b];
#pragma unroll
        for (int q = 0; q < 4; ++q) {
            int jj = j + q;
            int jf = jj - S_;
            float Iu = py0 * W_If[jf * 3] + py1 * W_If[jf * 3 + 1] + cc * W_If[jf * 3 + 2];
            float Ir = py0 * W_If[(S_ + jf) * 3] + py1 * W_If[(S_ + jf) * 3 + 1] + cc * W_If[(S_ + jf) * 3 + 2];
            float Ie = py0 * W_If[(2 * S_ + jf) * 3] + py1 * W_If[(2 * S_ + jf) * 3 + 1] + cc * W_If[(2 * S_ + jf) * 3 + 2];
            float u = fsigm(__half2float(Ru2[q]) + Iu + bias_u[jj]);
            float r = fsigm(__half2float(Rr2[q]) + Ir + bias_r[jj]);
            float e = ftanh(r * __half2float(Re2[q]) + Ie + bias_e[jj]);
            h[q] = u * ph[q] + (1.f - u) * e;
        }
    }

    *(float4*)(hidden_out + idx) = make_float4(h[0], h[1], h[2], h[3]);

    __half hh[4];
#pragma unroll
    for (int q = 0; q < 4; ++q) hh[q] = __float2half(h[q]);
    *(uint2*)(hid_h + idx) = *(uint2*)hh;
}

// ---------------- launch ----------------
extern "C" void kernel_launch(void* const* d_in, const int* in_sizes, int n_in,
                              void* d_out, int out_size)
{
    const float* prev_y      = (const float*)d_in[0];
    const float* prev_hidden = (const float*)d_in[1];
    const float* coarse      = (const float*)d_in[2];
    const float* W_Ru        = (const float*)d_in[3];
    const float* W_Rr        = (const float*)d_in[4];
    const float* W_Re        = (const float*)d_in[5];
    const float* W_Ic        = (const float*)d_in[6];
    const float* W_If        = (const float*)d_in[7];
    const float* W_O1        = (const float*)d_in[8];
    const float* b_O1        = (const float*)d_in[9];
    const float* W_O2        = (const float*)d_in[10];
    const float* b_O2        = (const float*)d_in[11];
    const float* W_O3        = (const float*)d_in[12];
    const float* b_O3        = (const float*)d_in[13];
    const float* W_O4        = (const float*)d_in[14];
    const float* b_O4        = (const float*)d_in[15];
    const float* bias_u      = (const float*)d_in[16];
    const float* bias_r      = (const float*)d_in[17];
    const float* bias_e      = (const float*)d_in[18];

    float* out        = (float*)d_out;
    float* out_coarse = out;
    float* hidden     = out + 2 * (size_t)B_ * Q_;

    __half *Rbuf, *Ah, *Hh, *Th, *Wh;
    cudaGetSymbolAddress((void**)&Rbuf, g_R);
    cudaGetSymbolAddress((void**)&Ah, g_Ah);
    cudaGetSymbolAddress((void**)&Hh, g_Hh);
    cudaGetSymbolAddress((void**)&Th, g_Th);
    cudaGetSymbolAddress((void**)&Wh, g_Wh);

    cudaFuncSetAttribute(gemm_mma<0, true>,  cudaFuncAttributeMaxDynamicSharedMemorySize, SMEM_TOTAL);
    cudaFuncSetAttribute(gemm_mma<2, false>, cudaFuncAttributeMaxDynamicSharedMemorySize, SMEM_TOTAL);
    cudaFuncSetAttribute(gemm_mma<1, false>, cudaFuncAttributeMaxDynamicSharedMemorySize, SMEM_TOTAL);

    const int NBS = B_ * S_;
    dim3 blk(256);

    // converts (3 launches)
    cvtW_kernel<<<(B_ * H_ / 4 + 255) / 256, 256>>>((const float4*)prev_hidden, Ah, B_ * H_ / 4);
    cvtWR3_kernel<<<(3 * H_ * H_ / 4 + 255) / 256, 256>>>((const float4*)W_Ru, (const float4*)W_Rr,
                                                          (const float4*)W_Re, Wh + OFF_WR);
    cvtW4_kernel<<<((2 * S_ * S_ + 2 * Q_ * S_) / 4 + 255) / 256, 256>>>(
        (const float4*)W_O1, (const float4*)W_O3, (const float4*)W_O2, (const float4*)W_O4,
        Wh + OFF_WO1);

    // fused recurrent projections -> R (fp16), N = 3*H = 2688
    dim3 g1(3 * H_ / 128, B_ / 128, 1);  // (21, 64)
    gemm_mma<0, true><<<g1, blk, SMEM_TOTAL>>>(Ah, H_, Wh + OFF_WR,
                                               3 * H_, H_, nullptr, nullptr,
                                               nullptr, Rbuf, H_, 0, 0, 0);

    // fused gates -> hidden (fp32 to d_out) + fp16 copy
    gate_kernel<<<(B_ * (H_ / 4) + 255) / 256, 256>>>(prev_y, prev_hidden, coarse, W_Ic, W_If,
                                                      bias_u, bias_r, bias_e, Rbuf, hidden, Hh);

    // relu(h_half @ W^T + b) -> fp16 scratch; z batches O1 / O3
    dim3 g2((S_ + 127) / 128, B_ / 128, 2);  // (4, 64, 2)
    gemm_mma<2, false><<<g2, blk, SMEM_TOTAL>>>(Hh, H_, Wh + OFF_WO1,
                                                S_, S_, b_O1, b_O3,
                                                nullptr, Th, S_,
                                                S_, S_ * S_, NBS);

    // logits -> d_out; z batches O2 / O4
    dim3 g3(Q_ / 128, B_ / 128, 2);  // (2, 64, 2)
    gemm_mma<1, false><<<g3, blk, SMEM_TOTAL>>>(Th, S_, Wh + OFF_WO2,
                                                Q_, S_, b_O2, b_O4,
                                                out_coarse, nullptr, Q_,
                                                NBS, Q_ * S_, B_ * Q_);
}